// round 7
// baseline (speedup 1.0000x reference)
#include <cuda_runtime.h>

#define IN_F 128
#define HF 64          // HEADS*OUT_F
#define RB 64          // rows per block
#define NT 256         // threads per block
#define TR 4           // rows per thread
#define NKP 64         // k-pairs

typedef unsigned long long ull;

// ---- scratch: in-degree flags as words ----
__device__ __align__(16) int g_flag[50048];

__device__ __forceinline__ ull ffma2(ull a, ull b, ull c) {
    ull d;
    asm("fma.rn.f32x2 %0, %1, %2, %3;" : "=l"(d) : "l"(a), "l"(b), "l"(c));
    return d;
}
__device__ __forceinline__ float2 unpack2(ull v) {
    float2 r;
    asm("mov.b64 {%0, %1}, %2;" : "=f"(r.x), "=f"(r.y) : "l"(v));
    return r;
}

// ---- K1: mark nodes with >=1 incoming edge (idempotent word stores) ----
__global__ __launch_bounds__(256) void k_mark(const int* __restrict__ tgt, int e) {
    int i = blockIdx.x * blockDim.x + threadIdx.x;
    int e4 = e >> 2;
    if (i < e4) {
        int4 t = ((const int4*)tgt)[i];
        g_flag[t.x] = 1; g_flag[t.y] = 1; g_flag[t.z] = 1; g_flag[t.w] = 1;
    }
    if (i == e4 && (e & 3)) {
        for (int j = e4 * 4; j < e; j++) g_flag[tgt[j]] = 1;
    }
}

// ---- K2: out = (x @ W) * flag + bias  (k-pair f32x2, zero-MOV inner loop) ----
// 256 threads: rg = tid>>4 (16 groups x 4 rows), cg = tid&15 (16 groups x 4 cols).
// acc[r][c] f32x2 lanes = (even-k partial, odd-k partial) for ONE output col.
// A-operand = (x[k],x[k+1]) straight from the x 16B load; B-operand from smem
// Ws2[kp][c] = (W[2kp][c], W[2kp+1][c]).
__global__ __launch_bounds__(NT, 2) void k_gemm(
    const float* __restrict__ x, const float* __restrict__ W,
    const float* __restrict__ bias, float* __restrict__ out, int n)
{
    __shared__ __align__(16) ull Ws2[NKP * HF];   // [kp][c], 32 KB

    const int tid = threadIdx.x;
    const int cg  = tid & 15;
    const int rg  = tid >> 4;
    const int base_row = blockIdx.x * RB + rg * TR;

    // ---- stage W into k-pair transposed layout (one-time) ----
    {
        unsigned* wsw = (unsigned*)Ws2;
#pragma unroll
        for (int j = 0; j < 8; j++) {
            int e = tid + NT * j;          // 2048 float4 total
            int k = e >> 4;
            int c = (e & 15) * 4;
            float4 v = *(const float4*)(W + (size_t)k * HF + c);
            unsigned* p = wsw + (k >> 1) * (HF * 2) + c * 2 + (k & 1);
            p[0] = __float_as_uint(v.x);
            p[2] = __float_as_uint(v.y);
            p[4] = __float_as_uint(v.z);
            p[6] = __float_as_uint(v.w);
        }
    }
    __syncthreads();

    // clamped base pointer; rows consecutive -> immediate offsets
    int brow = base_row;
    if (brow + (TR - 1) >= n) brow = (n >= TR) ? (n - TR) : 0;
    const float* xb0 = x + (size_t)brow * IN_F;

    ull acc[TR][4];
#pragma unroll
    for (int r = 0; r < TR; r++)
#pragma unroll
        for (int c = 0; c < 4; c++) acc[r][c] = 0ull;

    const ulonglong2* wsp = (const ulonglong2*)Ws2;   // idx = kp*32 + c/2

    ulonglong2 xa[TR], xb[TR];   // 16B of x = k-pairs (kp, kp+1)
#pragma unroll
    for (int r = 0; r < TR; r++)
        xa[r] = *(const ulonglong2*)(xb0 + r * IN_F);

    // one buffer = 4 k = 2 k-pairs
#define COMPUTE2KP(XR, KPB)                                                   \
    do {                                                                      \
        _Pragma("unroll")                                                     \
        for (int h = 0; h < 2; h++) {                                         \
            const int kp = (KPB) + h;                                         \
            ulonglong2 w01 = wsp[kp * 32 + cg * 2];                           \
            ulonglong2 w23 = wsp[kp * 32 + cg * 2 + 1];                       \
            _Pragma("unroll")                                                 \
            for (int r = 0; r < TR; r++) {                                    \
                ull xd = (h == 0) ? XR[r].x : XR[r].y;                        \
                acc[r][0] = ffma2(xd, w01.x, acc[r][0]);                      \
                acc[r][1] = ffma2(xd, w01.y, acc[r][1]);                      \
                acc[r][2] = ffma2(xd, w23.x, acc[r][2]);                      \
                acc[r][3] = ffma2(xd, w23.y, acc[r][3]);                      \
            }                                                                 \
        }                                                                     \
    } while (0)

#pragma unroll 1
    for (int it = 0; it < 16; it++) {          // 8 k per iteration
        const int k0 = it * 8;
#pragma unroll
        for (int r = 0; r < TR; r++)
            xb[r] = *(const ulonglong2*)(xb0 + r * IN_F + k0 + 4);
        COMPUTE2KP(xa, k0 / 2);
        const int nxt = (it == 15) ? 0 : k0 + 8;
#pragma unroll
        for (int r = 0; r < TR; r++)
            xa[r] = *(const ulonglong2*)(xb0 + r * IN_F + nxt);
        COMPUTE2KP(xb, k0 / 2 + 2);
    }
#undef COMPUTE2KP

    // ---- epilogue: out = (even+odd) * flag + bias ----
    float4 bv = __ldg((const float4*)bias + cg);

#pragma unroll
    for (int r = 0; r < TR; r++) {
        int row = base_row + r;
        if (row < n) {
            int ar = row - brow;   // differs from r only in clamped tail block
            float s = g_flag[row] ? 1.0f : 0.0f;
            float2 a0 = unpack2(acc[ar][0]);
            float2 a1 = unpack2(acc[ar][1]);
            float2 a2 = unpack2(acc[ar][2]);
            float2 a3 = unpack2(acc[ar][3]);
            float4 o;
            o.x = (a0.x + a0.y) * s + bv.x;
            o.y = (a1.x + a1.y) * s + bv.y;
            o.z = (a2.x + a2.y) * s + bv.z;
            o.w = (a3.x + a3.y) * s + bv.w;
            *(float4*)(out + (size_t)row * HF + cg * 4) = o;
        }
    }
}

extern "C" void kernel_launch(void* const* d_in, const int* in_sizes, int n_in,
                              void* d_out, int out_size)
{
    const float* x    = (const float*)d_in[0];
    const int*   ei   = (const int*)d_in[1];
    const float* W    = (const float*)d_in[2];
    const float* bias = (const float*)d_in[5];
    float* out = (float*)d_out;

    const int n = in_sizes[0] / IN_F;   // 50000
    const int e = in_sizes[1] / 2;      // 800000
    const int* tgt = ei + e;

    void* flag_ptr = nullptr;
    cudaGetSymbolAddress(&flag_ptr, g_flag);
    cudaMemsetAsync(flag_ptr, 0, sizeof(g_flag), 0);

    k_mark<<<(e / 4 + 255) / 256, 256>>>(tgt, e);
    k_gemm<<<(n + RB - 1) / RB, NT>>>(x, W, bias, out, n);
}

// round 8
// speedup vs baseline: 1.3577x; 1.3577x over previous
#include <cuda_runtime.h>

#define IN_F 128
#define HF 64          // HEADS*OUT_F
#define RB 64          // rows per block
#define NT 128         // threads per block
#define TR 4           // rows per thread (cols per thread = 8)

typedef unsigned long long ull;

// ---- scratch: in-degree flags as words ----
__device__ __align__(16) int g_flag[50048];

__device__ __forceinline__ ull ffma2(ull a, ull b, ull c) {
    ull d;
    asm("fma.rn.f32x2 %0, %1, %2, %3;" : "=l"(d) : "l"(a), "l"(b), "l"(c));
    return d;
}
__device__ __forceinline__ ull pack2(float lo, float hi) {
    ull d;
    asm("mov.b64 %0, {%1, %2};" : "=l"(d) : "f"(lo), "f"(hi));
    return d;
}
__device__ __forceinline__ float2 unpack2(ull v) {
    float2 r;
    asm("mov.b64 {%0, %1}, %2;" : "=f"(r.x), "=f"(r.y) : "l"(v));
    return r;
}

// ---- K1: mark nodes with >=1 incoming edge (idempotent word stores) ----
__global__ __launch_bounds__(256) void k_mark(const int* __restrict__ tgt, int e) {
    int i = blockIdx.x * blockDim.x + threadIdx.x;
    int e4 = e >> 2;
    if (i < e4) {
        int4 t = ((const int4*)tgt)[i];
        g_flag[t.x] = 1; g_flag[t.y] = 1; g_flag[t.z] = 1; g_flag[t.w] = 1;
    }
    if (i == e4 && (e & 3)) {
        for (int j = e4 * 4; j < e; j++) g_flag[tgt[j]] = 1;
    }
}

// ---- K2: out = (x @ W) * flag + bias ----
// k-pair f32x2: acc[r][c] lanes = (even-k partial, odd-k partial).
// A-operand = (x[2kp], x[2kp+1]) straight out of the x float4 load (zero MOV).
// B-operand from smem Ws2: 16B chunk for (kp, i, cg) holds cols (cg*8+2i, +1)
// packed as ((W[2kp][c],W[2kp+1][c]), ...), stored at position kp*32 + i*8 + cg
// -> per LDS.128 the 8 cg-lanes hit banks 0..31 exactly once: conflict-free.
// Threads: cg = tid&7 (8 col-groups x 8 cols), rg = tid>>3 (16 row-groups x 4).
__global__ __launch_bounds__(NT, 3) void k_gemm(
    const float* __restrict__ x, const float* __restrict__ W,
    const float* __restrict__ bias, float* __restrict__ out, int n)
{
    __shared__ __align__(16) ulonglong2 Ws2[2048];   // 32 KB

    const int tid = threadIdx.x;
    const int cg  = tid & 7;
    const int rg  = tid >> 3;
    const int base_row = blockIdx.x * RB + rg * TR;

    // ---- stage W (one-time): 2048 chunks, 16 per thread ----
#pragma unroll
    for (int j = 0; j < 16; j++) {
        int g  = tid + NT * j;
        int kp = g >> 5;
        int i  = (g >> 3) & 3;
        int c  = (g & 7) * 8 + 2 * i;
        float2 a = *(const float2*)(W + (size_t)(2 * kp)     * HF + c);
        float2 b = *(const float2*)(W + (size_t)(2 * kp + 1) * HF + c);
        ulonglong2 v;
        v.x = pack2(a.x, b.x);
        v.y = pack2(a.y, b.y);
        Ws2[g] = v;
    }
    __syncthreads();

    // clamped base pointer; rows consecutive -> immediate offsets
    int brow = base_row;
    if (brow + (TR - 1) >= n) brow = (n >= TR) ? (n - TR) : 0;
    const float* xb0 = x + (size_t)brow * IN_F;

    ull acc[TR][8];
#pragma unroll
    for (int r = 0; r < TR; r++)
#pragma unroll
        for (int c = 0; c < 8; c++) acc[r][c] = 0ull;

    ulonglong2 xa[TR], xb[TR];   // 16B of x = 2 k-pairs
#pragma unroll
    for (int r = 0; r < TR; r++)
        xa[r] = *(const ulonglong2*)(xb0 + r * IN_F);

    // COMPUTE for 2 k-pairs held in XR (.x -> kp KPB, .y -> kp KPB+1)
#define COMPUTE2KP(XR, KPB)                                                   \
    do {                                                                      \
        _Pragma("unroll")                                                     \
        for (int h = 0; h < 2; h++) {                                         \
            const int kp = (KPB) + h;                                         \
            ulonglong2 w0 = Ws2[kp * 32 + 0 * 8 + cg];                        \
            ulonglong2 w1 = Ws2[kp * 32 + 1 * 8 + cg];                        \
            ulonglong2 w2 = Ws2[kp * 32 + 2 * 8 + cg];                        \
            ulonglong2 w3 = Ws2[kp * 32 + 3 * 8 + cg];                        \
            _Pragma("unroll")                                                 \
            for (int r = 0; r < TR; r++) {                                    \
                ull xd = (h == 0) ? XR[r].x : XR[r].y;                        \
                acc[r][0] = ffma2(xd, w0.x, acc[r][0]);                       \
                acc[r][1] = ffma2(xd, w0.y, acc[r][1]);                       \
                acc[r][2] = ffma2(xd, w1.x, acc[r][2]);                       \
                acc[r][3] = ffma2(xd, w1.y, acc[r][3]);                       \
                acc[r][4] = ffma2(xd, w2.x, acc[r][4]);                       \
                acc[r][5] = ffma2(xd, w2.y, acc[r][5]);                       \
                acc[r][6] = ffma2(xd, w3.x, acc[r][6]);                       \
                acc[r][7] = ffma2(xd, w3.y, acc[r][7]);                       \
            }                                                                 \
        }                                                                     \
    } while (0)

#pragma unroll 1
    for (int it = 0; it < 16; it++) {      // 8 k (= 4 kp) per iteration
        const int k0 = it * 8;
#pragma unroll
        for (int r = 0; r < TR; r++)
            xb[r] = *(const ulonglong2*)(xb0 + r * IN_F + k0 + 4);
        COMPUTE2KP(xa, k0 / 2);
        const int nxt = (it == 15) ? 0 : k0 + 8;
#pragma unroll
        for (int r = 0; r < TR; r++)
            xa[r] = *(const ulonglong2*)(xb0 + r * IN_F + nxt);
        COMPUTE2KP(xb, k0 / 2 + 2);
    }
#undef COMPUTE2KP

    // ---- epilogue: out = (even+odd) * flag + bias ----
    float4 bv0 = __ldg((const float4*)(bias + cg * 8));
    float4 bv1 = __ldg((const float4*)(bias + cg * 8 + 4));

#pragma unroll
    for (int r = 0; r < TR; r++) {
        int row = base_row + r;
        if (row < n) {
            int ar = row - brow;   // differs from r only in clamped tail block
            float s = g_flag[row] ? 1.0f : 0.0f;
            float2 a0 = unpack2(acc[ar][0]);
            float2 a1 = unpack2(acc[ar][1]);
            float2 a2 = unpack2(acc[ar][2]);
            float2 a3 = unpack2(acc[ar][3]);
            float2 a4 = unpack2(acc[ar][4]);
            float2 a5 = unpack2(acc[ar][5]);
            float2 a6 = unpack2(acc[ar][6]);
            float2 a7 = unpack2(acc[ar][7]);
            float4 o0, o1;
            o0.x = (a0.x + a0.y) * s + bv0.x;
            o0.y = (a1.x + a1.y) * s + bv0.y;
            o0.z = (a2.x + a2.y) * s + bv0.z;
            o0.w = (a3.x + a3.y) * s + bv0.w;
            o1.x = (a4.x + a4.y) * s + bv1.x;
            o1.y = (a5.x + a5.y) * s + bv1.y;
            o1.z = (a6.x + a6.y) * s + bv1.z;
            o1.w = (a7.x + a7.y) * s + bv1.w;
            float* op = out + (size_t)row * HF + cg * 8;
            *(float4*)op       = o0;
            *(float4*)(op + 4) = o1;
        }
    }
}

extern "C" void kernel_launch(void* const* d_in, const int* in_sizes, int n_in,
                              void* d_out, int out_size)
{
    const float* x    = (const float*)d_in[0];
    const int*   ei   = (const int*)d_in[1];
    const float* W    = (const float*)d_in[2];
    const float* bias = (const float*)d_in[5];
    float* out = (float*)d_out;

    const int n = in_sizes[0] / IN_F;   // 50000
    const int e = in_sizes[1] / 2;      // 800000
    const int* tgt = ei + e;

    void* flag_ptr = nullptr;
    cudaGetSymbolAddress(&flag_ptr, g_flag);
    cudaMemsetAsync(flag_ptr, 0, sizeof(g_flag), 0);

    k_mark<<<(e / 4 + 255) / 256, 256>>>(tgt, e);
    k_gemm<<<(n + RB - 1) / RB, NT>>>(x, W, bias, out, n);
}